// round 15
// baseline (speedup 1.0000x reference)
#include <cuda_runtime.h>
#include <cuda_bf16.h>
#include <cstddef>
#include <cstdint>

// Problem constants
#define NLAYERS 2
#define BB 4
#define LL 2048
#define DD 512
#define NN 16
#define OO 512
#define MM (BB * LL)   // 8192 rows

// scan chunking
#define NCH 32
#define CL (LL / NCH)  // 64
#define SC_D 32        // d-columns per scan block

#define WSEG (DD * DD)   // 262144 elements per weight matrix

// ---------------- scratch buffers (no allocation allowed) ----------------
__device__ float g_dt[MM * DD];
__device__ float g_bc[MM * 2 * NN];
__device__ float g_y[MM * DD];
__device__ float g_y2[MM * DD];
__device__ float g_hA[MM * DD];
__device__ float g_hB[MM * DD];
__device__ float g_cA[BB * NCH * DD * NN];
__device__ float g_cH[BB * NCH * DD * NN];
__device__ uint32_t g_wr[5 * WSEG];   // tf32-rounded TRANSPOSED weights [n][k]

// ---------------- helpers ----------------
__device__ __forceinline__ float softplus_f(float v) {
    return fmaxf(v, 0.f) + log1pf(__expf(-fabsf(v)));
}

__device__ __forceinline__ float gelu_f(float v) {
    return 0.5f * v * (1.f + erff(v * 0.70710678118654752440f));
}

__device__ __forceinline__ float ex2f(float x) {
    float y;
    asm("ex2.approx.f32 %0, %1;" : "=f"(y) : "f"(x));
    return y;
}

#define LOG2E 1.4426950408889634f

__device__ __forceinline__ uint32_t f2tf32(float f) {
    uint32_t u;
    asm("cvt.rna.tf32.f32 %0, %1;" : "=r"(u) : "f"(f));
    return u;
}

__device__ __forceinline__ void cp_async16(void* smem, const void* gmem) {
    uint32_t s = (uint32_t)__cvta_generic_to_shared(smem);
    asm volatile("cp.async.cg.shared.global [%0], [%1], 16;" :: "r"(s), "l"(gmem));
}
__device__ __forceinline__ void cp_commit() {
    asm volatile("cp.async.commit_group;");
}
template <int N>
__device__ __forceinline__ void cp_wait() {
    asm volatile("cp.async.wait_group %0;" :: "n"(N));
}

__device__ __forceinline__ void ldmatrix_x4(uint32_t& r0, uint32_t& r1,
                                            uint32_t& r2, uint32_t& r3,
                                            uint32_t addr) {
    asm volatile("ldmatrix.sync.aligned.m8n8.x4.shared.b16 {%0,%1,%2,%3}, [%4];"
                 : "=r"(r0), "=r"(r1), "=r"(r2), "=r"(r3) : "r"(addr));
}

__device__ __forceinline__ void mma_tf32(float4& d,
                                         const uint32_t* a,
                                         uint32_t b0, uint32_t b1,
                                         const float4& c) {
    asm volatile(
        "mma.sync.aligned.m16n8k8.row.col.f32.tf32.tf32.f32 "
        "{%0,%1,%2,%3}, {%4,%5,%6,%7}, {%8,%9}, {%10,%11,%12,%13};"
        : "=f"(d.x), "=f"(d.y), "=f"(d.z), "=f"(d.w)
        : "r"(a[0]), "r"(a[1]), "r"(a[2]), "r"(a[3]),
          "r"(b0), "r"(b1),
          "f"(c.x), "f"(c.y), "f"(c.z), "f"(c.w));
}

// ---------------- weight prep: fp32 -> tf32 bits, TRANSPOSED to [n][k] ------
__global__ void prep_w(const float* __restrict__ wdt,
                       const float* __restrict__ wmix,
                       const float* __restrict__ wdec) {
    __shared__ uint32_t ts[32][33];
    const int mat = blockIdx.z;                       // 0..4
    const float* src = (mat < 2) ? wdt + (size_t)mat * WSEG
                     : (mat < 4) ? wmix + (size_t)(mat - 2) * WSEG
                                 : wdec;
    const int k0 = blockIdx.y * 32;
    const int nb = blockIdx.x * 32;
    const int tx = threadIdx.x;                       // 0..31
    const int ty = threadIdx.y;                       // 0..7
#pragma unroll
    for (int i = 0; i < 32; i += 8)
        ts[ty + i][tx] = f2tf32(src[(size_t)(k0 + ty + i) * DD + nb + tx]);
    __syncthreads();
    uint32_t* dst = g_wr + (size_t)mat * WSEG;
#pragma unroll
    for (int i = 0; i < 32; i += 8)
        dst[(size_t)(nb + ty + i) * DD + k0 + tx] = ts[tx][ty + i];
}

// ---------------- tensor-core GEMM: C = A[M,512] @ W[512,512] + bias ----------------
// CTA 128x64, k-tile 32, 8 warps (4M x 2N), warp tile 32x32, 2 CTAs/SM.
// A: LDG -> cvt -> STS [row][k] stride 36; fragments via ldmatrix.x4.
// B: pre-rounded TRANSPOSED tf32, cp.async into Bs[n][k] stride 36; ldmatrix.x4.
// EPI==1 additionally carries the fp32 B/C projection in blocks x==8
// (heterogeneous fusion: same input A, bc output layout [row][32]).
#define AS_STRIDE 36
#define BS_STRIDE 36
#define AS_TILE (128 * AS_STRIDE)
#define BS_TILE (64 * BS_STRIDE)
#define GEMM_SMEM_BYTES ((2 * AS_TILE + 2 * BS_TILE) * 4)   // 55296
#define GEMM1_SMEM_BYTES (32 * DD * 4)                      // 65536 (bc staging)

template <int EPI>
__global__ void __launch_bounds__(256, 2)
gemm_tc(const float* __restrict__ A,
        const uint32_t* __restrict__ Wr,
        const float* __restrict__ bias,
        float* __restrict__ C,
        const float* __restrict__ WB, const float* __restrict__ bB,
        const float* __restrict__ WC, const float* __restrict__ bC,
        float* __restrict__ BCout) {
    extern __shared__ uint32_t smem[];

    if (EPI == 1 && blockIdx.x == 8) {
        // -------- fp32 B/C projection path (bit-identical to old bc_kernel) ----
        float* xs = (float*)smem;   // [32][512]
        const int tid = threadIdx.x;
        const int m0 = blockIdx.y * 128;
        const int c = tid & 31;
        const int grp = tid >> 5;
        const int n = c & 15;
        const float* Wp = (c < 16) ? WB : WC;
        const float bias2 = (c < 16) ? bB[n] : bC[n];

        for (int sb = 0; sb < 4; sb++) {
            const int row0 = m0 + sb * 32;
            if (sb) __syncthreads();   // previous compute done before overwrite
            for (int i = tid; i < 32 * (DD / 4); i += 256) {
                int r = i >> 7;
                int c4 = i & 127;
                ((float4*)(xs + r * DD))[c4] =
                    ((const float4*)(A + (size_t)(row0 + r) * DD))[c4];
            }
            __syncthreads();

            float acc0 = bias2, acc1 = bias2, acc2 = bias2, acc3 = bias2;
            const float* x0 = xs + (grp * 4 + 0) * DD;
            const float* x1 = xs + (grp * 4 + 1) * DD;
            const float* x2 = xs + (grp * 4 + 2) * DD;
            const float* x3 = xs + (grp * 4 + 3) * DD;
#pragma unroll 4
            for (int k0 = 0; k0 < DD; k0 += 4) {
                const float w0 = __ldg(Wp + (k0 + 0) * NN + n);
                const float w1 = __ldg(Wp + (k0 + 1) * NN + n);
                const float w2 = __ldg(Wp + (k0 + 2) * NN + n);
                const float w3 = __ldg(Wp + (k0 + 3) * NN + n);
                float4 v;
                v = *(const float4*)(x0 + k0);
                acc0 = fmaf(v.x, w0, acc0); acc0 = fmaf(v.y, w1, acc0);
                acc0 = fmaf(v.z, w2, acc0); acc0 = fmaf(v.w, w3, acc0);
                v = *(const float4*)(x1 + k0);
                acc1 = fmaf(v.x, w0, acc1); acc1 = fmaf(v.y, w1, acc1);
                acc1 = fmaf(v.z, w2, acc1); acc1 = fmaf(v.w, w3, acc1);
                v = *(const float4*)(x2 + k0);
                acc2 = fmaf(v.x, w0, acc2); acc2 = fmaf(v.y, w1, acc2);
                acc2 = fmaf(v.z, w2, acc2); acc2 = fmaf(v.w, w3, acc2);
                v = *(const float4*)(x3 + k0);
                acc3 = fmaf(v.x, w0, acc3); acc3 = fmaf(v.y, w1, acc3);
                acc3 = fmaf(v.z, w2, acc3); acc3 = fmaf(v.w, w3, acc3);
            }
            BCout[(size_t)(row0 + grp * 4 + 0) * 32 + c] = acc0;
            BCout[(size_t)(row0 + grp * 4 + 1) * 32 + c] = acc1;
            BCout[(size_t)(row0 + grp * 4 + 2) * 32 + c] = acc2;
            BCout[(size_t)(row0 + grp * 4 + 3) * 32 + c] = acc3;
        }
        return;
    }

    // -------- tensor-core GEMM path --------
    uint32_t* As = smem;
    uint32_t* Bs = smem + 2 * AS_TILE;

    const int tid  = threadIdx.x;
    const int lane = tid & 31;
    const int warp = tid >> 5;
    const int g    = lane >> 2;
    const int tig  = lane & 3;
    const int mBase = (warp >> 1) * 32;
    const int nBase = (warp & 1) * 32;

    const int m0 = blockIdx.y * 128;
    const int n0 = blockIdx.x * 64;

    const int aRow = tid >> 3;
    const int aKc  = (tid & 7) * 4;
    const int bN  = tid >> 2;
    const int bKc = (tid & 3) * 4;

    const uint32_t smem_u32 = (uint32_t)__cvta_generic_to_shared(smem);

    const int tl   = lane >> 3;
    const int lrow = lane & 7;
    const int arow = mBase + ((tl & 1) << 3) + lrow;
    const int akoff = (tl >> 1) << 2;
    const uint32_t aAddrBase = smem_u32 + (uint32_t)((arow * AS_STRIDE + akoff) * 4);

    const int j_loc = (lane >> 4) & 1;
    const int khalf = (lane >> 3) & 1;
    const uint32_t bTileBase = smem_u32 + (uint32_t)(2 * AS_TILE * 4);
    uint32_t bAddr[2];
#pragma unroll
    for (int jp = 0; jp < 2; jp++) {
        const int n = nBase + 16 * jp + 8 * j_loc + lrow;
        bAddr[jp] = bTileBase + (uint32_t)((n * BS_STRIDE + 4 * khalf) * 4);
    }

    float4 acc[2][4];
#pragma unroll
    for (int t = 0; t < 2; t++)
#pragma unroll
        for (int j = 0; j < 4; j++) acc[t][j] = make_float4(0.f, 0.f, 0.f, 0.f);

    float4 aR[4];

    auto ldg_A = [&](int kt) {
#pragma unroll
        for (int i = 0; i < 4; i++) {
            int row = aRow + 32 * i;
            aR[i] = *(const float4*)(A + (size_t)(m0 + row) * 512 + kt * 32 + aKc);
        }
    };

    auto sts_A = [&](int stage) {
        uint32_t* as = As + stage * AS_TILE;
#pragma unroll
        for (int i = 0; i < 4; i++) {
            int row = aRow + 32 * i;
            uint4 v;
            v.x = f2tf32(aR[i].x); v.y = f2tf32(aR[i].y);
            v.z = f2tf32(aR[i].z); v.w = f2tf32(aR[i].w);
            *(uint4*)(as + row * AS_STRIDE + aKc) = v;
        }
    };

    auto cp_B = [&](int kt, int stage) {
        uint32_t* bs = Bs + stage * BS_TILE;
#pragma unroll
        for (int i = 0; i < 2; i++) {
            int kc = bKc + 16 * i;
            cp_async16(bs + bN * BS_STRIDE + kc,
                       Wr + (size_t)(n0 + bN) * 512 + kt * 32 + kc);
        }
    };

    cp_B(0, 0); cp_commit();
    ldg_A(0);
    sts_A(0);
    cp_wait<0>();
    __syncthreads();

    const int NKT = 512 / 32;
    for (int kt = 0; kt < NKT; kt++) {
        if (kt + 1 < NKT) {
            ldg_A(kt + 1);
            cp_B(kt + 1, (kt + 1) & 1);
            cp_commit();
        }

        const uint32_t aStage = aAddrBase + (uint32_t)((kt & 1) * AS_TILE * 4);
        const uint32_t bOff = (uint32_t)((kt & 1) * BS_TILE * 4);

#pragma unroll
        for (int s = 0; s < 4; s++) {
            uint32_t afr[2][4];
            const uint32_t aaddr = aStage + (uint32_t)(s * 32);
            ldmatrix_x4(afr[0][0], afr[0][1], afr[0][2], afr[0][3], aaddr);
            ldmatrix_x4(afr[1][0], afr[1][1], afr[1][2], afr[1][3],
                        aaddr + (uint32_t)(16 * AS_STRIDE * 4));
            uint32_t bfr[2][4];
            ldmatrix_x4(bfr[0][0], bfr[0][1], bfr[0][2], bfr[0][3],
                        bAddr[0] + bOff + (uint32_t)(s * 32));
            ldmatrix_x4(bfr[1][0], bfr[1][1], bfr[1][2], bfr[1][3],
                        bAddr[1] + bOff + (uint32_t)(s * 32));
#pragma unroll
            for (int jp = 0; jp < 2; jp++) {
#pragma unroll
                for (int jl = 0; jl < 2; jl++) {
                    const int j = 2 * jp + jl;
                    const uint32_t b0 = bfr[jp][2 * jl];
                    const uint32_t b1 = bfr[jp][2 * jl + 1];
                    mma_tf32(acc[0][j], afr[0], b0, b1, acc[0][j]);
                    mma_tf32(acc[1][j], afr[1], b0, b1, acc[1][j]);
                }
            }
        }

        if (kt + 1 < NKT) {
            sts_A((kt + 1) & 1);
            cp_wait<0>();
            __syncthreads();
        }
    }

#pragma unroll
    for (int t = 0; t < 2; t++) {
#pragma unroll
        for (int j = 0; j < 4; j++) {
            const int row = m0 + mBase + 16 * t + g;
            const int col = n0 + nBase + 8 * j + tig * 2;
            float b0 = bias[col], b1 = bias[col + 1];
            float v0 = acc[t][j].x + b0;
            float v1 = acc[t][j].y + b1;
            float v2 = acc[t][j].z + b0;
            float v3 = acc[t][j].w + b1;
            if (EPI == 1) {
                v0 = softplus_f(v0); v1 = softplus_f(v1);
                v2 = softplus_f(v2); v3 = softplus_f(v3);
            }
            *(float2*)(C + (size_t)row * 512 + col) = make_float2(v0, v1);
            *(float2*)(C + (size_t)(row + 8) * 512 + col) = make_float2(v2, v3);
        }
    }
}

// ---------------- scan pass 1: per-chunk carry (A_prod, h_end) ----------------
__global__ void __launch_bounds__(128)
scan_carry(const float* __restrict__ X,
           const float* __restrict__ DT,
           const float* __restrict__ BC,
           const float* __restrict__ A_log,
           float* __restrict__ cA,
           float* __restrict__ cH) {
    __shared__ float sdx[CL][2 * SC_D];
    __shared__ float sB[CL][16];

    const int tid = threadIdx.x;
    const int dl = tid >> 2;
    const int n0 = (tid & 3) * 4;
    const int d0 = blockIdx.x * SC_D;
    const int d  = d0 + dl;
    const int ch = blockIdx.y;
    const int b  = blockIdx.z;

    const float* Xb  = X  + (size_t)b * LL * DD + (size_t)ch * CL * DD;
    const float* DTb = DT + (size_t)b * LL * DD + (size_t)ch * CL * DD;
    const float* BCb = BC + (size_t)b * LL * 32 + (size_t)ch * CL * 32;

#pragma unroll
    for (int i = 0; i < 4; i++) {
        int idx = tid + 128 * i;
        int l = idx >> 3;
        int q = (idx & 7) * 4;
        const float4 dt4 = *(const float4*)(DTb + (size_t)l * DD + d0 + q);
        const float4 x4  = *(const float4*)(Xb  + (size_t)l * DD + d0 + q);
        float4 v0, v1;
        v0.x = dt4.x; v0.y = dt4.x * x4.x; v0.z = dt4.y; v0.w = dt4.y * x4.y;
        v1.x = dt4.z; v1.y = dt4.z * x4.z; v1.z = dt4.w; v1.w = dt4.w * x4.w;
        *(float4*)&sdx[l][2 * q]     = v0;
        *(float4*)&sdx[l][2 * q + 4] = v1;
    }
#pragma unroll
    for (int i = 0; i < 2; i++) {
        int idx = tid + 128 * i;
        int l = idx >> 2;
        int q = (idx & 3) * 4;
        *(float4*)&sB[l][q] = *(const float4*)(BCb + l * 32 + q);
    }
    __syncthreads();

    float Ac2[4];
#pragma unroll
    for (int j = 0; j < 4; j++)
        Ac2[j] = -__expf(A_log[d * NN + n0 + j]) * LOG2E;

    float h[4] = {0.f, 0.f, 0.f, 0.f};
    float Ap[4] = {1.f, 1.f, 1.f, 1.f};

#pragma unroll 4
    for (int l = 0; l < CL; l++) {
        const float2 dd = *(const float2*)&sdx[l][2 * dl];
        const float4 B4 = *(const float4*)&sB[l][n0];
        float a0 = ex2f(dd.x * Ac2[0]);
        float a1 = ex2f(dd.x * Ac2[1]);
        float a2 = ex2f(dd.x * Ac2[2]);
        float a3 = ex2f(dd.x * Ac2[3]);
        h[0] = fmaf(a0, h[0], dd.y * B4.x); Ap[0] *= a0;
        h[1] = fmaf(a1, h[1], dd.y * B4.y); Ap[1] *= a1;
        h[2] = fmaf(a2, h[2], dd.y * B4.z); Ap[2] *= a2;
        h[3] = fmaf(a3, h[3], dd.y * B4.w); Ap[3] *= a3;
    }
    const size_t o = ((size_t)(b * NCH + ch) * DD + d) * NN + n0;
    *(float4*)(cA + o) = make_float4(Ap[0], Ap[1], Ap[2], Ap[3]);
    *(float4*)(cH + o) = make_float4(h[0], h[1], h[2], h[3]);
}

// ---------------- scan pass 2: per-chunk scan + C-contract ----------------
#define SCAN_SMEM_BYTES ((CL * 2 * SC_D + CL * 16 * 2) * 4)   // 24576
__global__ void __launch_bounds__(128)
scan_apply(const float* __restrict__ X,
           const float* __restrict__ DT,
           const float* __restrict__ BC,
           const float* __restrict__ A_log,
           const float* __restrict__ Dskip,
           const float* __restrict__ cA,
           const float* __restrict__ cH,
           float* __restrict__ Y) {
    extern __shared__ float ssm[];
    float* sdx = ssm;                          // CL * 64 interleaved (dt|p, x)
    float* sB  = sdx + CL * 2 * SC_D;
    float* sC  = sB + CL * 16;

    const int tid = threadIdx.x;
    const int dl = tid >> 2;
    const int n0 = (tid & 3) * 4;
    const int d0 = blockIdx.x * SC_D;
    const int d  = d0 + dl;
    const int ch = blockIdx.y;
    const int b  = blockIdx.z;

    const float* Xb  = X  + (size_t)b * LL * DD + (size_t)ch * CL * DD;
    const float* DTb = DT + (size_t)b * LL * DD + (size_t)ch * CL * DD;
    const float* BCb = BC + (size_t)b * LL * 32 + (size_t)ch * CL * 32;
    float*       Yb  = Y  + (size_t)b * LL * DD + (size_t)ch * CL * DD;

#pragma unroll
    for (int i = 0; i < 4; i++) {
        int idx = tid + 128 * i;
        int l = idx >> 3;
        int q = (idx & 7) * 4;
        const float4 dt4 = *(const float4*)(DTb + (size_t)l * DD + d0 + q);
        const float4 x4  = *(const float4*)(Xb  + (size_t)l * DD + d0 + q);
        float4 v0, v1;
        v0.x = dt4.x; v0.y = x4.x; v0.z = dt4.y; v0.w = x4.y;
        v1.x = dt4.z; v1.y = x4.z; v1.z = dt4.w; v1.w = x4.w;
        *(float4*)(sdx + l * 2 * SC_D + 2 * q)     = v0;
        *(float4*)(sdx + l * 2 * SC_D + 2 * q + 4) = v1;
    }
#pragma unroll
    for (int i = 0; i < 2; i++) {
        int idx = tid + 128 * i;
        int l = idx >> 2;
        int q = (idx & 3) * 4;
        *(float4*)(sB + l * 16 + q) = *(const float4*)(BCb + l * 32 + q);
        *(float4*)(sC + l * 16 + q) = *(const float4*)(BCb + l * 32 + 16 + q);
    }

    float h[4] = {0.f, 0.f, 0.f, 0.f};
    {
        const size_t base = ((size_t)b * NCH * DD + d) * NN + n0;
        for (int c = 0; c < ch; c++) {
            const size_t o = base + (size_t)c * (DD * NN);
            const float4 A4 = *(const float4*)(cA + o);
            const float4 H4 = *(const float4*)(cH + o);
            h[0] = fmaf(A4.x, h[0], H4.x);
            h[1] = fmaf(A4.y, h[1], H4.y);
            h[2] = fmaf(A4.z, h[2], H4.z);
            h[3] = fmaf(A4.w, h[3], H4.w);
        }
    }

    float Ac2[4];
#pragma unroll
    for (int j = 0; j < 4; j++)
        Ac2[j] = -__expf(A_log[d * NN + n0 + j]) * LOG2E;

    __syncthreads();

#pragma unroll 4
    for (int l = 0; l < CL; l++) {
        const float2 dd = *(const float2*)(sdx + l * 2 * SC_D + 2 * dl);
        const float dtx = dd.x * dd.y;
        const float4 B4 = *(const float4*)(sB + l * 16 + n0);
        const float4 C4 = *(const float4*)(sC + l * 16 + n0);
        float a0 = ex2f(dd.x * Ac2[0]);
        float a1 = ex2f(dd.x * Ac2[1]);
        float a2 = ex2f(dd.x * Ac2[2]);
        float a3 = ex2f(dd.x * Ac2[3]);
        h[0] = fmaf(a0, h[0], dtx * B4.x);
        h[1] = fmaf(a1, h[1], dtx * B4.y);
        h[2] = fmaf(a2, h[2], dtx * B4.z);
        h[3] = fmaf(a3, h[3], dtx * B4.w);
        float p01 = fmaf(C4.y, h[1], C4.x * h[0]);
        float p23 = fmaf(C4.w, h[3], C4.z * h[2]);
        float p = p01 + p23;
        p += __shfl_xor_sync(0xffffffffu, p, 1, 4);
        p += __shfl_xor_sync(0xffffffffu, p, 2, 4);
        if (n0 == 0) sdx[l * 2 * SC_D + 2 * dl] = p;
    }
    __syncthreads();

#pragma unroll
    for (int i = 0; i < 4; i++) {
        int idx = tid + 128 * i;
        int l = idx >> 3;
        int q = (idx & 7) * 4;
        const float4 dk = *(const float4*)(Dskip + d0 + q);
        const float4 f0 = *(const float4*)(sdx + l * 2 * SC_D + 2 * q);
        const float4 f1 = *(const float4*)(sdx + l * 2 * SC_D + 2 * q + 4);
        float4 o;
        o.x = gelu_f(fmaf(dk.x, f0.y, f0.x));
        o.y = gelu_f(fmaf(dk.y, f0.w, f0.z));
        o.z = gelu_f(fmaf(dk.z, f1.y, f1.x));
        o.w = gelu_f(fmaf(dk.w, f1.w, f1.z));
        *(float4*)(Yb + (size_t)l * DD + d0 + q) = o;
    }
}

// ---------------- layernorm + residual: one warp per row ----------------
__global__ void __launch_bounds__(256)
ln_res_kernel(const float* __restrict__ Hin,
              const float* __restrict__ Y2,
              const float* __restrict__ g,
              const float* __restrict__ bb,
              float* __restrict__ Hout) {
    const int lane = threadIdx.x & 31;
    const int wrp  = threadIdx.x >> 5;
    const int row  = blockIdx.x * 8 + wrp;
    const float* yr = Y2 + (size_t)row * DD;

    float4 v[4];
    float s = 0.f;
#pragma unroll
    for (int j = 0; j < 4; j++) {
        v[j] = *(const float4*)(yr + lane * 4 + j * 128);
        s += (v[j].x + v[j].y) + (v[j].z + v[j].w);
    }
#pragma unroll
    for (int o = 16; o > 0; o >>= 1) s += __shfl_xor_sync(0xffffffffu, s, o);
    const float mean = s * (1.f / DD);

    float sq = 0.f;
#pragma unroll
    for (int j = 0; j < 4; j++) {
        float d0 = v[j].x - mean, d1 = v[j].y - mean;
        float d2 = v[j].z - mean, d3 = v[j].w - mean;
        sq += (d0 * d0 + d1 * d1) + (d2 * d2 + d3 * d3);
    }
#pragma unroll
    for (int o = 16; o > 0; o >>= 1) sq += __shfl_xor_sync(0xffffffffu, sq, o);
    const float rstd = rsqrtf(sq * (1.f / DD) + 1e-5f);

#pragma unroll
    for (int j = 0; j < 4; j++) {
        const int col = lane * 4 + j * 128;
        const float4 gg = *(const float4*)(g + col);
        const float4 bv = *(const float4*)(bb + col);
        const float4 hi = *(const float4*)(Hin + (size_t)row * DD + col);
        float4 o;
        o.x = hi.x + (v[j].x - mean) * rstd * gg.x + bv.x;
        o.y = hi.y + (v[j].y - mean) * rstd * gg.y + bv.y;
        o.z = hi.z + (v[j].z - mean) * rstd * gg.z + bv.z;
        o.w = hi.w + (v[j].w - mean) * rstd * gg.w + bv.w;
        *(float4*)(Hout + (size_t)row * DD + col) = o;
    }
}

// ---------------- launch ----------------
extern "C" void kernel_launch(void* const* d_in, const int* in_sizes, int n_in,
                              void* d_out, int out_size) {
    const float* x      = (const float*)d_in[0];
    const float* A_log  = (const float*)d_in[1];
    const float* W_B    = (const float*)d_in[2];
    const float* b_B    = (const float*)d_in[3];
    const float* W_C    = (const float*)d_in[4];
    const float* b_C    = (const float*)d_in[5];
    const float* W_dt   = (const float*)d_in[6];
    const float* b_dt   = (const float*)d_in[7];
    const float* D_skip = (const float*)d_in[8];
    const float* W_mix  = (const float*)d_in[9];
    const float* b_mix  = (const float*)d_in[10];
    const float* ln_g   = (const float*)d_in[11];
    const float* ln_b   = (const float*)d_in[12];
    const float* W_dec  = (const float*)d_in[13];
    const float* b_dec  = (const float*)d_in[14];
    float* out = (float*)d_out;

    float *p_dt, *p_bc, *p_y, *p_y2, *p_hA, *p_hB, *p_cA, *p_cH;
    uint32_t* p_wr;
    cudaGetSymbolAddress((void**)&p_dt, g_dt);
    cudaGetSymbolAddress((void**)&p_bc, g_bc);
    cudaGetSymbolAddress((void**)&p_y,  g_y);
    cudaGetSymbolAddress((void**)&p_y2, g_y2);
    cudaGetSymbolAddress((void**)&p_hA, g_hA);
    cudaGetSymbolAddress((void**)&p_hB, g_hB);
    cudaGetSymbolAddress((void**)&p_cA, g_cA);
    cudaGetSymbolAddress((void**)&p_cH, g_cH);
    cudaGetSymbolAddress((void**)&p_wr, g_wr);

    cudaFuncSetAttribute(gemm_tc<0>, cudaFuncAttributeMaxDynamicSharedMemorySize,
                         GEMM_SMEM_BYTES);
    cudaFuncSetAttribute(gemm_tc<1>, cudaFuncAttributeMaxDynamicSharedMemorySize,
                         GEMM1_SMEM_BYTES);
    cudaFuncSetAttribute(scan_apply, cudaFuncAttributeMaxDynamicSharedMemorySize,
                         SCAN_SMEM_BYTES);

    // pre-round + transpose all GEMM weights (bit-identical tf32 values)
    {
        dim3 pgrid(DD / 32, DD / 32, 5);
        dim3 pblk(32, 8);
        prep_w<<<pgrid, pblk>>>(W_dt, W_mix, W_dec);
    }

    const dim3 gemm1Grid(9, MM / 128);            // 8 GEMM tiles + 1 bc column
    const dim3 gemmGrid(DD / 64, MM / 128);       // (8, 64)
    const dim3 scanGrid(DD / SC_D, NCH, BB);      // (16, 32, 4)

    const float* hin = x;
    float* houts[2] = { p_hA, p_hB };

    for (int l = 0; l < NLAYERS; l++) {
        // fused: dt = softplus(hin @ W_dt + b_dt)  AND  Bm/Cm projection
        gemm_tc<1><<<gemm1Grid, 256, GEMM1_SMEM_BYTES>>>(
            hin, p_wr + (size_t)l * WSEG, b_dt + l * DD, p_dt,
            W_B + (size_t)l * DD * NN, b_B + l * NN,
            W_C + (size_t)l * DD * NN, b_C + l * NN, p_bc);
        scan_carry<<<scanGrid, 128>>>(hin, p_dt, p_bc,
                                      A_log + (size_t)l * DD * NN, p_cA, p_cH);
        scan_apply<<<scanGrid, 128, SCAN_SMEM_BYTES>>>(
            hin, p_dt, p_bc, A_log + (size_t)l * DD * NN,
            D_skip + l * DD, p_cA, p_cH, p_y);
        gemm_tc<0><<<gemmGrid, 256, GEMM_SMEM_BYTES>>>(
            p_y, p_wr + (size_t)(2 + l) * WSEG, b_mix + l * DD, p_y2,
            nullptr, nullptr, nullptr, nullptr, nullptr);
        ln_res_kernel<<<MM / 8, 256>>>(hin, p_y2, ln_g + l * DD, ln_b + l * DD,
                                       houts[l]);
        hin = houts[l];
    }

    gemm_tc<0><<<gemmGrid, 256, GEMM_SMEM_BYTES>>>(hin, p_wr + (size_t)4 * WSEG,
                                                   b_dec, out,
                                                   nullptr, nullptr, nullptr,
                                                   nullptr, nullptr);
}

// round 16
// speedup vs baseline: 1.6018x; 1.6018x over previous
#include <cuda_runtime.h>
#include <cuda_bf16.h>
#include <cstddef>
#include <cstdint>

// Problem constants
#define NLAYERS 2
#define BB 4
#define LL 2048
#define DD 512
#define NN 16
#define OO 512
#define MM (BB * LL)   // 8192 rows

// scan chunking
#define NCH 32
#define CL (LL / NCH)  // 64
#define SC_D 32        // d-columns per scan block

#define WSEG (DD * DD)   // 262144 elements per weight matrix

// ---------------- scratch buffers (no allocation allowed) ----------------
__device__ float g_dt[MM * DD];
__device__ float g_bc[MM * 2 * NN];
__device__ float g_y2[MM * DD];
__device__ float g_hA[MM * DD];
__device__ float g_hB[MM * DD];
__device__ float g_cA[BB * NCH * DD * NN];
__device__ float g_cH[BB * NCH * DD * NN];
__device__ uint32_t g_wr[5 * WSEG];   // tf32-rounded TRANSPOSED weights [n][k]
__device__ uint32_t g_xr[MM * DD];    // tf32-rounded x
__device__ uint32_t g_yr[MM * DD];    // tf32-rounded scan output (post-gelu)
__device__ uint32_t g_hr[MM * DD];    // tf32-rounded layer output

// ---------------- helpers ----------------
__device__ __forceinline__ float softplus_f(float v) {
    return fmaxf(v, 0.f) + log1pf(__expf(-fabsf(v)));
}

__device__ __forceinline__ float gelu_f(float v) {
    return 0.5f * v * (1.f + erff(v * 0.70710678118654752440f));
}

__device__ __forceinline__ float ex2f(float x) {
    float y;
    asm("ex2.approx.f32 %0, %1;" : "=f"(y) : "f"(x));
    return y;
}

#define LOG2E 1.4426950408889634f

__device__ __forceinline__ uint32_t f2tf32(float f) {
    uint32_t u;
    asm("cvt.rna.tf32.f32 %0, %1;" : "=r"(u) : "f"(f));
    return u;
}

__device__ __forceinline__ void cp_async16(void* smem, const void* gmem) {
    uint32_t s = (uint32_t)__cvta_generic_to_shared(smem);
    asm volatile("cp.async.cg.shared.global [%0], [%1], 16;" :: "r"(s), "l"(gmem));
}
__device__ __forceinline__ void cp_commit() {
    asm volatile("cp.async.commit_group;");
}
template <int N>
__device__ __forceinline__ void cp_wait() {
    asm volatile("cp.async.wait_group %0;" :: "n"(N));
}

__device__ __forceinline__ void ldmatrix_x4(uint32_t& r0, uint32_t& r1,
                                            uint32_t& r2, uint32_t& r3,
                                            uint32_t addr) {
    asm volatile("ldmatrix.sync.aligned.m8n8.x4.shared.b16 {%0,%1,%2,%3}, [%4];"
                 : "=r"(r0), "=r"(r1), "=r"(r2), "=r"(r3) : "r"(addr));
}

__device__ __forceinline__ void mma_tf32(float4& d,
                                         const uint32_t* a,
                                         uint32_t b0, uint32_t b1,
                                         const float4& c) {
    asm volatile(
        "mma.sync.aligned.m16n8k8.row.col.f32.tf32.tf32.f32 "
        "{%0,%1,%2,%3}, {%4,%5,%6,%7}, {%8,%9}, {%10,%11,%12,%13};"
        : "=f"(d.x), "=f"(d.y), "=f"(d.z), "=f"(d.w)
        : "r"(a[0]), "r"(a[1]), "r"(a[2]), "r"(a[3]),
          "r"(b0), "r"(b1),
          "f"(c.x), "f"(c.y), "f"(c.z), "f"(c.w));
}

// ---------------- weight prep: fp32 -> tf32 bits, TRANSPOSED to [n][k] ------
__global__ void prep_w(const float* __restrict__ wdt,
                       const float* __restrict__ wmix,
                       const float* __restrict__ wdec) {
    __shared__ uint32_t ts[32][33];
    const int mat = blockIdx.z;                       // 0..4
    const float* src = (mat < 2) ? wdt + (size_t)mat * WSEG
                     : (mat < 4) ? wmix + (size_t)(mat - 2) * WSEG
                                 : wdec;
    const int k0 = blockIdx.y * 32;
    const int nb = blockIdx.x * 32;
    const int tx = threadIdx.x;                       // 0..31
    const int ty = threadIdx.y;                       // 0..7
#pragma unroll
    for (int i = 0; i < 32; i += 8)
        ts[ty + i][tx] = f2tf32(src[(size_t)(k0 + ty + i) * DD + nb + tx]);
    __syncthreads();
    uint32_t* dst = g_wr + (size_t)mat * WSEG;
#pragma unroll
    for (int i = 0; i < 32; i += 8)
        dst[(size_t)(nb + ty + i) * DD + k0 + tx] = ts[tx][ty + i];
}

// ---------------- x prep: elementwise tf32 rounding of the input ----------------
__global__ void prep_x(const float* __restrict__ x) {
    const int i = blockIdx.x * 256 + threadIdx.x;     // float4 index
    const float4 v = ((const float4*)x)[i];
    uint4 o;
    o.x = f2tf32(v.x); o.y = f2tf32(v.y);
    o.z = f2tf32(v.z); o.w = f2tf32(v.w);
    ((uint4*)g_xr)[i] = o;
}

// ---------------- tensor-core GEMM: C = Ar[M,512] @ W[512,512] + bias ----------------
// CTA 128x64, k-tile 32, 8 warps (4M x 2N), warp tile 32x32, 2 CTAs/SM.
// BOTH operands pre-rounded tf32 in gmem -> pure cp.async loaders, no cvt/reg
// staging in the kernel at all. Fragments via ldmatrix.x4 for A and B.
#define AS_STRIDE 36
#define BS_STRIDE 36
#define AS_TILE (128 * AS_STRIDE)
#define BS_TILE (64 * BS_STRIDE)
#define GEMM_SMEM_BYTES ((2 * AS_TILE + 2 * BS_TILE) * 4)   // 55296

template <int EPI>
__global__ void __launch_bounds__(256, 2)
gemm_tc(const uint32_t* __restrict__ Ar,
        const uint32_t* __restrict__ Wr,
        const float* __restrict__ bias,
        float* __restrict__ C) {
    extern __shared__ uint32_t smem[];
    uint32_t* As = smem;
    uint32_t* Bs = smem + 2 * AS_TILE;

    const int tid  = threadIdx.x;
    const int lane = tid & 31;
    const int warp = tid >> 5;
    const int g    = lane >> 2;
    const int tig  = lane & 3;
    const int mBase = (warp >> 1) * 32;
    const int nBase = (warp & 1) * 32;

    const int m0 = blockIdx.y * 128;
    const int n0 = blockIdx.x * 64;

    const int aRow = tid >> 3;
    const int aKc  = (tid & 7) * 4;
    const int bN  = tid >> 2;
    const int bKc = (tid & 3) * 4;

    const uint32_t smem_u32 = (uint32_t)__cvta_generic_to_shared(smem);

    const int tl   = lane >> 3;
    const int lrow = lane & 7;
    const int arow = mBase + ((tl & 1) << 3) + lrow;
    const int akoff = (tl >> 1) << 2;
    const uint32_t aAddrBase = smem_u32 + (uint32_t)((arow * AS_STRIDE + akoff) * 4);

    const int j_loc = (lane >> 4) & 1;
    const int khalf = (lane >> 3) & 1;
    const uint32_t bTileBase = smem_u32 + (uint32_t)(2 * AS_TILE * 4);
    uint32_t bAddr[2];
#pragma unroll
    for (int jp = 0; jp < 2; jp++) {
        const int n = nBase + 16 * jp + 8 * j_loc + lrow;
        bAddr[jp] = bTileBase + (uint32_t)((n * BS_STRIDE + 4 * khalf) * 4);
    }

    float4 acc[2][4];
#pragma unroll
    for (int t = 0; t < 2; t++)
#pragma unroll
        for (int j = 0; j < 4; j++) acc[t][j] = make_float4(0.f, 0.f, 0.f, 0.f);

    auto cp_A = [&](int kt, int stage) {
        uint32_t* as = As + stage * AS_TILE;
#pragma unroll
        for (int i = 0; i < 4; i++) {
            int row = aRow + 32 * i;
            cp_async16(as + row * AS_STRIDE + aKc,
                       Ar + (size_t)(m0 + row) * 512 + kt * 32 + aKc);
        }
    };

    auto cp_B = [&](int kt, int stage) {
        uint32_t* bs = Bs + stage * BS_TILE;
#pragma unroll
        for (int i = 0; i < 2; i++) {
            int kc = bKc + 16 * i;
            cp_async16(bs + bN * BS_STRIDE + kc,
                       Wr + (size_t)(n0 + bN) * 512 + kt * 32 + kc);
        }
    };

    cp_A(0, 0);
    cp_B(0, 0);
    cp_commit();
    cp_wait<0>();
    __syncthreads();

    const int NKT = 512 / 32;
    for (int kt = 0; kt < NKT; kt++) {
        if (kt + 1 < NKT) {
            cp_A(kt + 1, (kt + 1) & 1);
            cp_B(kt + 1, (kt + 1) & 1);
            cp_commit();
        }

        const uint32_t aStage = aAddrBase + (uint32_t)((kt & 1) * AS_TILE * 4);
        const uint32_t bOff = (uint32_t)((kt & 1) * BS_TILE * 4);

#pragma unroll
        for (int s = 0; s < 4; s++) {
            uint32_t afr[2][4];
            const uint32_t aaddr = aStage + (uint32_t)(s * 32);
            ldmatrix_x4(afr[0][0], afr[0][1], afr[0][2], afr[0][3], aaddr);
            ldmatrix_x4(afr[1][0], afr[1][1], afr[1][2], afr[1][3],
                        aaddr + (uint32_t)(16 * AS_STRIDE * 4));
            uint32_t bfr[2][4];
            ldmatrix_x4(bfr[0][0], bfr[0][1], bfr[0][2], bfr[0][3],
                        bAddr[0] + bOff + (uint32_t)(s * 32));
            ldmatrix_x4(bfr[1][0], bfr[1][1], bfr[1][2], bfr[1][3],
                        bAddr[1] + bOff + (uint32_t)(s * 32));
#pragma unroll
            for (int jp = 0; jp < 2; jp++) {
#pragma unroll
                for (int jl = 0; jl < 2; jl++) {
                    const int j = 2 * jp + jl;
                    const uint32_t b0 = bfr[jp][2 * jl];
                    const uint32_t b1 = bfr[jp][2 * jl + 1];
                    mma_tf32(acc[0][j], afr[0], b0, b1, acc[0][j]);
                    mma_tf32(acc[1][j], afr[1], b0, b1, acc[1][j]);
                }
            }
        }

        if (kt + 1 < NKT) {
            cp_wait<0>();
            __syncthreads();
        }
    }

#pragma unroll
    for (int t = 0; t < 2; t++) {
#pragma unroll
        for (int j = 0; j < 4; j++) {
            const int row = m0 + mBase + 16 * t + g;
            const int col = n0 + nBase + 8 * j + tig * 2;
            float b0 = bias[col], b1 = bias[col + 1];
            float v0 = acc[t][j].x + b0;
            float v1 = acc[t][j].y + b1;
            float v2 = acc[t][j].z + b0;
            float v3 = acc[t][j].w + b1;
            if (EPI == 1) {
                v0 = softplus_f(v0); v1 = softplus_f(v1);
                v2 = softplus_f(v2); v3 = softplus_f(v3);
            }
            *(float2*)(C + (size_t)row * 512 + col) = make_float2(v0, v1);
            *(float2*)(C + (size_t)(row + 8) * 512 + col) = make_float2(v2, v3);
        }
    }
}

// ---------------- B/C projection v2: [M,512] @ [512,16] x2 ----------------
#define BC_SMEM_BYTES (32 * DD * 4)
__global__ void bc_kernel(const float* __restrict__ X,
                          const float* __restrict__ WB, const float* __restrict__ bB,
                          const float* __restrict__ WC, const float* __restrict__ bC,
                          float* __restrict__ BC) {
    extern __shared__ float xs[];   // [32][512]
    const int tid = threadIdx.x;
    const int row0 = blockIdx.x * 32;

    for (int i = tid; i < 32 * (DD / 4); i += 256) {
        int r = i >> 7;
        int c4 = i & 127;
        ((float4*)(xs + r * DD))[c4] =
            ((const float4*)(X + (size_t)(row0 + r) * DD))[c4];
    }
    __syncthreads();

    const int c = tid & 31;
    const int grp = tid >> 5;
    const int n = c & 15;
    const float* Wp = (c < 16) ? WB : WC;
    const float bias = (c < 16) ? bB[n] : bC[n];

    float acc0 = bias, acc1 = bias, acc2 = bias, acc3 = bias;
    const float* x0 = xs + (grp * 4 + 0) * DD;
    const float* x1 = xs + (grp * 4 + 1) * DD;
    const float* x2 = xs + (grp * 4 + 2) * DD;
    const float* x3 = xs + (grp * 4 + 3) * DD;

#pragma unroll 4
    for (int k0 = 0; k0 < DD; k0 += 4) {
        const float w0 = __ldg(Wp + (k0 + 0) * NN + n);
        const float w1 = __ldg(Wp + (k0 + 1) * NN + n);
        const float w2 = __ldg(Wp + (k0 + 2) * NN + n);
        const float w3 = __ldg(Wp + (k0 + 3) * NN + n);
        float4 v;
        v = *(const float4*)(x0 + k0);
        acc0 = fmaf(v.x, w0, acc0); acc0 = fmaf(v.y, w1, acc0);
        acc0 = fmaf(v.z, w2, acc0); acc0 = fmaf(v.w, w3, acc0);
        v = *(const float4*)(x1 + k0);
        acc1 = fmaf(v.x, w0, acc1); acc1 = fmaf(v.y, w1, acc1);
        acc1 = fmaf(v.z, w2, acc1); acc1 = fmaf(v.w, w3, acc1);
        v = *(const float4*)(x2 + k0);
        acc2 = fmaf(v.x, w0, acc2); acc2 = fmaf(v.y, w1, acc2);
        acc2 = fmaf(v.z, w2, acc2); acc2 = fmaf(v.w, w3, acc2);
        v = *(const float4*)(x3 + k0);
        acc3 = fmaf(v.x, w0, acc3); acc3 = fmaf(v.y, w1, acc3);
        acc3 = fmaf(v.z, w2, acc3); acc3 = fmaf(v.w, w3, acc3);
    }
    BC[(size_t)(row0 + grp * 4 + 0) * 32 + c] = acc0;
    BC[(size_t)(row0 + grp * 4 + 1) * 32 + c] = acc1;
    BC[(size_t)(row0 + grp * 4 + 2) * 32 + c] = acc2;
    BC[(size_t)(row0 + grp * 4 + 3) * 32 + c] = acc3;
}

// ---------------- scan pass 1: per-chunk carry (A_prod, h_end) ----------------
__global__ void __launch_bounds__(128)
scan_carry(const float* __restrict__ X,
           const float* __restrict__ DT,
           const float* __restrict__ BC,
           const float* __restrict__ A_log,
           float* __restrict__ cA,
           float* __restrict__ cH) {
    __shared__ float sdx[CL][2 * SC_D];
    __shared__ float sB[CL][16];

    const int tid = threadIdx.x;
    const int dl = tid >> 2;
    const int n0 = (tid & 3) * 4;
    const int d0 = blockIdx.x * SC_D;
    const int d  = d0 + dl;
    const int ch = blockIdx.y;
    const int b  = blockIdx.z;

    const float* Xb  = X  + (size_t)b * LL * DD + (size_t)ch * CL * DD;
    const float* DTb = DT + (size_t)b * LL * DD + (size_t)ch * CL * DD;
    const float* BCb = BC + (size_t)b * LL * 32 + (size_t)ch * CL * 32;

#pragma unroll
    for (int i = 0; i < 4; i++) {
        int idx = tid + 128 * i;
        int l = idx >> 3;
        int q = (idx & 7) * 4;
        const float4 dt4 = *(const float4*)(DTb + (size_t)l * DD + d0 + q);
        const float4 x4  = *(const float4*)(Xb  + (size_t)l * DD + d0 + q);
        float4 v0, v1;
        v0.x = dt4.x; v0.y = dt4.x * x4.x; v0.z = dt4.y; v0.w = dt4.y * x4.y;
        v1.x = dt4.z; v1.y = dt4.z * x4.z; v1.z = dt4.w; v1.w = dt4.w * x4.w;
        *(float4*)&sdx[l][2 * q]     = v0;
        *(float4*)&sdx[l][2 * q + 4] = v1;
    }
#pragma unroll
    for (int i = 0; i < 2; i++) {
        int idx = tid + 128 * i;
        int l = idx >> 2;
        int q = (idx & 3) * 4;
        *(float4*)&sB[l][q] = *(const float4*)(BCb + l * 32 + q);
    }
    __syncthreads();

    float Ac2[4];
#pragma unroll
    for (int j = 0; j < 4; j++)
        Ac2[j] = -__expf(A_log[d * NN + n0 + j]) * LOG2E;

    float h[4] = {0.f, 0.f, 0.f, 0.f};
    float Ap[4] = {1.f, 1.f, 1.f, 1.f};

#pragma unroll 4
    for (int l = 0; l < CL; l++) {
        const float2 dd = *(const float2*)&sdx[l][2 * dl];
        const float4 B4 = *(const float4*)&sB[l][n0];
        float a0 = ex2f(dd.x * Ac2[0]);
        float a1 = ex2f(dd.x * Ac2[1]);
        float a2 = ex2f(dd.x * Ac2[2]);
        float a3 = ex2f(dd.x * Ac2[3]);
        h[0] = fmaf(a0, h[0], dd.y * B4.x); Ap[0] *= a0;
        h[1] = fmaf(a1, h[1], dd.y * B4.y); Ap[1] *= a1;
        h[2] = fmaf(a2, h[2], dd.y * B4.z); Ap[2] *= a2;
        h[3] = fmaf(a3, h[3], dd.y * B4.w); Ap[3] *= a3;
    }
    const size_t o = ((size_t)(b * NCH + ch) * DD + d) * NN + n0;
    *(float4*)(cA + o) = make_float4(Ap[0], Ap[1], Ap[2], Ap[3]);
    *(float4*)(cH + o) = make_float4(h[0], h[1], h[2], h[3]);
}

// ---------------- scan pass 2: per-chunk scan + C-contract ----------------
// Output written as tf32-rounded bits (g_yr) - only the mix GEMM consumes it.
#define SCAN_SMEM_BYTES ((CL * 2 * SC_D + CL * 16 * 2) * 4)   // 24576
__global__ void __launch_bounds__(128)
scan_apply(const float* __restrict__ X,
           const float* __restrict__ DT,
           const float* __restrict__ BC,
           const float* __restrict__ A_log,
           const float* __restrict__ Dskip,
           const float* __restrict__ cA,
           const float* __restrict__ cH,
           uint32_t* __restrict__ Yr) {
    extern __shared__ float ssm[];
    float* sdx = ssm;                          // CL * 64 interleaved (dt|p, x)
    float* sB  = sdx + CL * 2 * SC_D;
    float* sC  = sB + CL * 16;

    const int tid = threadIdx.x;
    const int dl = tid >> 2;
    const int n0 = (tid & 3) * 4;
    const int d0 = blockIdx.x * SC_D;
    const int d  = d0 + dl;
    const int ch = blockIdx.y;
    const int b  = blockIdx.z;

    const float* Xb  = X  + (size_t)b * LL * DD + (size_t)ch * CL * DD;
    const float* DTb = DT + (size_t)b * LL * DD + (size_t)ch * CL * DD;
    const float* BCb = BC + (size_t)b * LL * 32 + (size_t)ch * CL * 32;
    uint32_t*    Yb  = Yr + (size_t)b * LL * DD + (size_t)ch * CL * DD;

#pragma unroll
    for (int i = 0; i < 4; i++) {
        int idx = tid + 128 * i;
        int l = idx >> 3;
        int q = (idx & 7) * 4;
        const float4 dt4 = *(const float4*)(DTb + (size_t)l * DD + d0 + q);
        const float4 x4  = *(const float4*)(Xb  + (size_t)l * DD + d0 + q);
        float4 v0, v1;
        v0.x = dt4.x; v0.y = x4.x; v0.z = dt4.y; v0.w = x4.y;
        v1.x = dt4.z; v1.y = x4.z; v1.z = dt4.w; v1.w = x4.w;
        *(float4*)(sdx + l * 2 * SC_D + 2 * q)     = v0;
        *(float4*)(sdx + l * 2 * SC_D + 2 * q + 4) = v1;
    }
#pragma unroll
    for (int i = 0; i < 2; i++) {
        int idx = tid + 128 * i;
        int l = idx >> 2;
        int q = (idx & 3) * 4;
        *(float4*)(sB + l * 16 + q) = *(const float4*)(BCb + l * 32 + q);
        *(float4*)(sC + l * 16 + q) = *(const float4*)(BCb + l * 32 + 16 + q);
    }

    float h[4] = {0.f, 0.f, 0.f, 0.f};
    {
        const size_t base = ((size_t)b * NCH * DD + d) * NN + n0;
        for (int c = 0; c < ch; c++) {
            const size_t o = base + (size_t)c * (DD * NN);
            const float4 A4 = *(const float4*)(cA + o);
            const float4 H4 = *(const float4*)(cH + o);
            h[0] = fmaf(A4.x, h[0], H4.x);
            h[1] = fmaf(A4.y, h[1], H4.y);
            h[2] = fmaf(A4.z, h[2], H4.z);
            h[3] = fmaf(A4.w, h[3], H4.w);
        }
    }

    float Ac2[4];
#pragma unroll
    for (int j = 0; j < 4; j++)
        Ac2[j] = -__expf(A_log[d * NN + n0 + j]) * LOG2E;

    __syncthreads();

#pragma unroll 4
    for (int l = 0; l < CL; l++) {
        const float2 dd = *(const float2*)(sdx + l * 2 * SC_D + 2 * dl);
        const float dtx = dd.x * dd.y;
        const float4 B4 = *(const float4*)(sB + l * 16 + n0);
        const float4 C4 = *(const float4*)(sC + l * 16 + n0);
        float a0 = ex2f(dd.x * Ac2[0]);
        float a1 = ex2f(dd.x * Ac2[1]);
        float a2 = ex2f(dd.x * Ac2[2]);
        float a3 = ex2f(dd.x * Ac2[3]);
        h[0] = fmaf(a0, h[0], dtx * B4.x);
        h[1] = fmaf(a1, h[1], dtx * B4.y);
        h[2] = fmaf(a2, h[2], dtx * B4.z);
        h[3] = fmaf(a3, h[3], dtx * B4.w);
        float p01 = fmaf(C4.y, h[1], C4.x * h[0]);
        float p23 = fmaf(C4.w, h[3], C4.z * h[2]);
        float p = p01 + p23;
        p += __shfl_xor_sync(0xffffffffu, p, 1, 4);
        p += __shfl_xor_sync(0xffffffffu, p, 2, 4);
        if (n0 == 0) sdx[l * 2 * SC_D + 2 * dl] = p;
    }
    __syncthreads();

    // cooperative writeback: GELU(fma(dsk,x,p)) rounded to tf32 bits
#pragma unroll
    for (int i = 0; i < 4; i++) {
        int idx = tid + 128 * i;
        int l = idx >> 3;
        int q = (idx & 7) * 4;
        const float4 dk = *(const float4*)(Dskip + d0 + q);
        const float4 f0 = *(const float4*)(sdx + l * 2 * SC_D + 2 * q);
        const float4 f1 = *(const float4*)(sdx + l * 2 * SC_D + 2 * q + 4);
        uint4 o;
        o.x = f2tf32(gelu_f(fmaf(dk.x, f0.y, f0.x)));
        o.y = f2tf32(gelu_f(fmaf(dk.y, f0.w, f0.z)));
        o.z = f2tf32(gelu_f(fmaf(dk.z, f1.y, f1.x)));
        o.w = f2tf32(gelu_f(fmaf(dk.w, f1.w, f1.z)));
        *(uint4*)(Yb + (size_t)l * DD + d0 + q) = o;
    }
}

// ---------------- layernorm + residual: one warp per row ----------------
// Writes fp32 Hout AND tf32-rounded Hr (GEMM input copy).
__global__ void __launch_bounds__(256)
ln_res_kernel(const float* __restrict__ Hin,
              const float* __restrict__ Y2,
              const float* __restrict__ g,
              const float* __restrict__ bb,
              float* __restrict__ Hout,
              uint32_t* __restrict__ Hr) {
    const int lane = threadIdx.x & 31;
    const int wrp  = threadIdx.x >> 5;
    const int row  = blockIdx.x * 8 + wrp;
    const float* yr = Y2 + (size_t)row * DD;

    float4 v[4];
    float s = 0.f;
#pragma unroll
    for (int j = 0; j < 4; j++) {
        v[j] = *(const float4*)(yr + lane * 4 + j * 128);
        s += (v[j].x + v[j].y) + (v[j].z + v[j].w);
    }
#pragma unroll
    for (int o = 16; o > 0; o >>= 1) s += __shfl_xor_sync(0xffffffffu, s, o);
    const float mean = s * (1.f / DD);

    float sq = 0.f;
#pragma unroll
    for (int j = 0; j < 4; j++) {
        float d0 = v[j].x - mean, d1 = v[j].y - mean;
        float d2 = v[j].z - mean, d3 = v[j].w - mean;
        sq += (d0 * d0 + d1 * d1) + (d2 * d2 + d3 * d3);
    }
#pragma unroll
    for (int o = 16; o > 0; o >>= 1) sq += __shfl_xor_sync(0xffffffffu, sq, o);
    const float rstd = rsqrtf(sq * (1.f / DD) + 1e-5f);

#pragma unroll
    for (int j = 0; j < 4; j++) {
        const int col = lane * 4 + j * 128;
        const float4 gg = *(const float4*)(g + col);
        const float4 bv = *(const float4*)(bb + col);
        const float4 hi = *(const float4*)(Hin + (size_t)row * DD + col);
        float4 o;
        o.x = hi.x + (v[j].x - mean) * rstd * gg.x + bv.x;
        o.y = hi.y + (v[j].y - mean) * rstd * gg.y + bv.y;
        o.z = hi.z + (v[j].z - mean) * rstd * gg.z + bv.z;
        o.w = hi.w + (v[j].w - mean) * rstd * gg.w + bv.w;
        *(float4*)(Hout + (size_t)row * DD + col) = o;
        uint4 r;
        r.x = f2tf32(o.x); r.y = f2tf32(o.y);
        r.z = f2tf32(o.z); r.w = f2tf32(o.w);
        *(uint4*)(Hr + (size_t)row * DD + col) = r;
    }
}

// ---------------- launch ----------------
extern "C" void kernel_launch(void* const* d_in, const int* in_sizes, int n_in,
                              void* d_out, int out_size) {
    const float* x      = (const float*)d_in[0];
    const float* A_log  = (const float*)d_in[1];
    const float* W_B    = (const float*)d_in[2];
    const float* b_B    = (const float*)d_in[3];
    const float* W_C    = (const float*)d_in[4];
    const float* b_C    = (const float*)d_in[5];
    const float* W_dt   = (const float*)d_in[6];
    const float* b_dt   = (const float*)d_in[7];
    const float* D_skip = (const float*)d_in[8];
    const float* W_mix  = (const float*)d_in[9];
    const float* b_mix  = (const float*)d_in[10];
    const float* ln_g   = (const float*)d_in[11];
    const float* ln_b   = (const float*)d_in[12];
    const float* W_dec  = (const float*)d_in[13];
    const float* b_dec  = (const float*)d_in[14];
    float* out = (float*)d_out;

    float *p_dt, *p_bc, *p_y2, *p_hA, *p_hB, *p_cA, *p_cH;
    uint32_t *p_wr, *p_xr, *p_yr, *p_hr;
    cudaGetSymbolAddress((void**)&p_dt, g_dt);
    cudaGetSymbolAddress((void**)&p_bc, g_bc);
    cudaGetSymbolAddress((void**)&p_y2, g_y2);
    cudaGetSymbolAddress((void**)&p_hA, g_hA);
    cudaGetSymbolAddress((void**)&p_hB, g_hB);
    cudaGetSymbolAddress((void**)&p_cA, g_cA);
    cudaGetSymbolAddress((void**)&p_cH, g_cH);
    cudaGetSymbolAddress((void**)&p_wr, g_wr);
    cudaGetSymbolAddress((void**)&p_xr, g_xr);
    cudaGetSymbolAddress((void**)&p_yr, g_yr);
    cudaGetSymbolAddress((void**)&p_hr, g_hr);

    cudaFuncSetAttribute(gemm_tc<0>, cudaFuncAttributeMaxDynamicSharedMemorySize,
                         GEMM_SMEM_BYTES);
    cudaFuncSetAttribute(gemm_tc<1>, cudaFuncAttributeMaxDynamicSharedMemorySize,
                         GEMM_SMEM_BYTES);
    cudaFuncSetAttribute(bc_kernel, cudaFuncAttributeMaxDynamicSharedMemorySize,
                         BC_SMEM_BYTES);
    cudaFuncSetAttribute(scan_apply, cudaFuncAttributeMaxDynamicSharedMemorySize,
                         SCAN_SMEM_BYTES);

    // pre-round + transpose weights; pre-round x  (bit-identical tf32 values)
    {
        dim3 pgrid(DD / 32, DD / 32, 5);
        dim3 pblk(32, 8);
        prep_w<<<pgrid, pblk>>>(W_dt, W_mix, W_dec);
        prep_x<<<MM * DD / 4 / 256, 256>>>(x);
    }

    const dim3 gemmGrid(DD / 64, MM / 128);       // (8, 64) = 512 CTAs
    const dim3 scanGrid(DD / SC_D, NCH, BB);      // (16, 32, 4)

    const float* hin = x;
    const uint32_t* hinr = p_xr;
    float* houts[2] = { p_hA, p_hB };

    for (int l = 0; l < NLAYERS; l++) {
        gemm_tc<1><<<gemmGrid, 256, GEMM_SMEM_BYTES>>>(
            hinr, p_wr + (size_t)l * WSEG, b_dt + l * DD, p_dt);
        bc_kernel<<<MM / 32, 256, BC_SMEM_BYTES>>>(
            hin, W_B + (size_t)l * DD * NN, b_B + l * NN,
            W_C + (size_t)l * DD * NN, b_C + l * NN, p_bc);
        scan_carry<<<scanGrid, 128>>>(hin, p_dt, p_bc,
                                      A_log + (size_t)l * DD * NN, p_cA, p_cH);
        scan_apply<<<scanGrid, 128, SCAN_SMEM_BYTES>>>(
            hin, p_dt, p_bc, A_log + (size_t)l * DD * NN,
            D_skip + l * DD, p_cA, p_cH, p_yr);
        gemm_tc<0><<<gemmGrid, 256, GEMM_SMEM_BYTES>>>(
            p_yr, p_wr + (size_t)(2 + l) * WSEG, b_mix + l * DD, p_y2);
        ln_res_kernel<<<MM / 8, 256>>>(hin, p_y2, ln_g + l * DD, ln_b + l * DD,
                                       houts[l], p_hr);
        hin = houts[l];
        hinr = p_hr;
    }

    gemm_tc<0><<<gemmGrid, 256, GEMM_SMEM_BYTES>>>(p_hr, p_wr + (size_t)4 * WSEG,
                                                   b_dec, out);
}

// round 17
// speedup vs baseline: 1.8498x; 1.1548x over previous
#include <cuda_runtime.h>
#include <cuda_bf16.h>
#include <cstddef>
#include <cstdint>

// Problem constants
#define NLAYERS 2
#define BB 4
#define LL 2048
#define DD 512
#define NN 16
#define OO 512
#define MM (BB * LL)   // 8192 rows

// scan chunking
#define NCH 32
#define CL (LL / NCH)  // 64
#define SC_D 32        // d-columns per scan block

#define WSEG (DD * DD)   // 262144 elements per weight matrix

// ---------------- scratch buffers (no allocation allowed) ----------------
__device__ float g_dt[MM * DD];
__device__ float g_bc[MM * 2 * NN];
__device__ float g_y2[MM * DD];
__device__ float g_hA[MM * DD];
__device__ float g_hB[MM * DD];
__device__ float g_cA[BB * NCH * DD * NN];
__device__ float g_cH[BB * NCH * DD * NN];
__device__ uint32_t g_wr[5 * WSEG];     // tf32-rounded TRANSPOSED weights [n][k]
__device__ uint32_t g_xr[MM * DD];      // tf32 hi of x
__device__ uint32_t g_xl[MM * DD];      // tf32 lo of x
__device__ uint32_t g_yr[MM * DD];      // tf32 scan output (post-gelu)
__device__ uint32_t g_hr[MM * DD];      // tf32 hi of layer output
__device__ uint32_t g_hl[MM * DD];      // tf32 lo of layer output
__device__ uint32_t g_bcw[NLAYERS * 2 * 32 * DD]; // bc weights [l][hi/lo][n=32][k=512]

// ---------------- helpers ----------------
__device__ __forceinline__ float softplus_f(float v) {
    return fmaxf(v, 0.f) + log1pf(__expf(-fabsf(v)));
}

__device__ __forceinline__ float gelu_f(float v) {
    return 0.5f * v * (1.f + erff(v * 0.70710678118654752440f));
}

__device__ __forceinline__ float ex2f(float x) {
    float y;
    asm("ex2.approx.f32 %0, %1;" : "=f"(y) : "f"(x));
    return y;
}

#define LOG2E 1.4426950408889634f

__device__ __forceinline__ uint32_t f2tf32(float f) {
    uint32_t u;
    asm("cvt.rna.tf32.f32 %0, %1;" : "=r"(u) : "f"(f));
    return u;
}

__device__ __forceinline__ void cp_async16(void* smem, const void* gmem) {
    uint32_t s = (uint32_t)__cvta_generic_to_shared(smem);
    asm volatile("cp.async.cg.shared.global [%0], [%1], 16;" :: "r"(s), "l"(gmem));
}
__device__ __forceinline__ void cp_commit() {
    asm volatile("cp.async.commit_group;");
}
template <int N>
__device__ __forceinline__ void cp_wait() {
    asm volatile("cp.async.wait_group %0;" :: "n"(N));
}

__device__ __forceinline__ void ldmatrix_x4(uint32_t& r0, uint32_t& r1,
                                            uint32_t& r2, uint32_t& r3,
                                            uint32_t addr) {
    asm volatile("ldmatrix.sync.aligned.m8n8.x4.shared.b16 {%0,%1,%2,%3}, [%4];"
                 : "=r"(r0), "=r"(r1), "=r"(r2), "=r"(r3) : "r"(addr));
}

__device__ __forceinline__ void mma_tf32(float4& d,
                                         const uint32_t* a,
                                         uint32_t b0, uint32_t b1,
                                         const float4& c) {
    asm volatile(
        "mma.sync.aligned.m16n8k8.row.col.f32.tf32.tf32.f32 "
        "{%0,%1,%2,%3}, {%4,%5,%6,%7}, {%8,%9}, {%10,%11,%12,%13};"
        : "=f"(d.x), "=f"(d.y), "=f"(d.z), "=f"(d.w)
        : "r"(a[0]), "r"(a[1]), "r"(a[2]), "r"(a[3]),
          "r"(b0), "r"(b1),
          "f"(c.x), "f"(c.y), "f"(c.z), "f"(c.w));
}

// ---------------- weight prep: fp32 -> tf32 bits, TRANSPOSED to [n][k] ------
__global__ void prep_w(const float* __restrict__ wdt,
                       const float* __restrict__ wmix,
                       const float* __restrict__ wdec) {
    __shared__ uint32_t ts[32][33];
    const int mat = blockIdx.z;                       // 0..4
    const float* src = (mat < 2) ? wdt + (size_t)mat * WSEG
                     : (mat < 4) ? wmix + (size_t)(mat - 2) * WSEG
                                 : wdec;
    const int k0 = blockIdx.y * 32;
    const int nb = blockIdx.x * 32;
    const int tx = threadIdx.x;                       // 0..31
    const int ty = threadIdx.y;                       // 0..7
#pragma unroll
    for (int i = 0; i < 32; i += 8)
        ts[ty + i][tx] = f2tf32(src[(size_t)(k0 + ty + i) * DD + nb + tx]);
    __syncthreads();
    uint32_t* dst = g_wr + (size_t)mat * WSEG;
#pragma unroll
    for (int i = 0; i < 32; i += 8)
        dst[(size_t)(nb + ty + i) * DD + k0 + tx] = ts[tx][ty + i];
}

// ---------------- x prep: hi/lo tf32 split of the input ----------------
__global__ void prep_x(const float* __restrict__ x) {
    const int i = blockIdx.x * 256 + threadIdx.x;     // float4 index
    const float4 v = ((const float4*)x)[i];
    uint4 hi, lo;
    hi.x = f2tf32(v.x); hi.y = f2tf32(v.y);
    hi.z = f2tf32(v.z); hi.w = f2tf32(v.w);
    lo.x = f2tf32(v.x - __uint_as_float(hi.x));
    lo.y = f2tf32(v.y - __uint_as_float(hi.y));
    lo.z = f2tf32(v.z - __uint_as_float(hi.z));
    lo.w = f2tf32(v.w - __uint_as_float(hi.w));
    ((uint4*)g_xr)[i] = hi;
    ((uint4*)g_xl)[i] = lo;
}

// ---------------- bc weight prep: [l][k][16]x2 -> hi/lo [l][part][n=32][k] ---
__global__ void prep_bcw(const float* __restrict__ WB,
                         const float* __restrict__ WC) {
    const int idx = blockIdx.x * 256 + threadIdx.x;   // NLAYERS*32*512
    const int l = idx >> 14;
    const int r = idx & 16383;
    const int n = r >> 9;
    const int k = r & 511;
    const float* src = (n < 16) ? WB + (size_t)l * DD * NN
                                : WC + (size_t)l * DD * NN;
    const float w = src[k * NN + (n & 15)];
    const uint32_t hi = f2tf32(w);
    const uint32_t lo = f2tf32(w - __uint_as_float(hi));
    g_bcw[((size_t)(l * 2 + 0) * 32 + n) * DD + k] = hi;
    g_bcw[((size_t)(l * 2 + 1) * 32 + n) * DD + k] = lo;
}

// ---------------- tensor-core GEMM: C = Ar[M,512] @ W[512,512] + bias ----------------
#define AS_STRIDE 36
#define BS_STRIDE 36
#define AS_TILE (128 * AS_STRIDE)
#define BS_TILE (64 * BS_STRIDE)
#define GEMM_SMEM_BYTES ((2 * AS_TILE + 2 * BS_TILE) * 4)   // 55296

template <int EPI>
__global__ void __launch_bounds__(256, 2)
gemm_tc(const uint32_t* __restrict__ Ar,
        const uint32_t* __restrict__ Wr,
        const float* __restrict__ bias,
        float* __restrict__ C) {
    extern __shared__ uint32_t smem[];
    uint32_t* As = smem;
    uint32_t* Bs = smem + 2 * AS_TILE;

    const int tid  = threadIdx.x;
    const int lane = tid & 31;
    const int warp = tid >> 5;
    const int g    = lane >> 2;
    const int tig  = lane & 3;
    const int mBase = (warp >> 1) * 32;
    const int nBase = (warp & 1) * 32;

    const int m0 = blockIdx.y * 128;
    const int n0 = blockIdx.x * 64;

    const int aRow = tid >> 3;
    const int aKc  = (tid & 7) * 4;
    const int bN  = tid >> 2;
    const int bKc = (tid & 3) * 4;

    const uint32_t smem_u32 = (uint32_t)__cvta_generic_to_shared(smem);

    const int tl   = lane >> 3;
    const int lrow = lane & 7;
    const int arow = mBase + ((tl & 1) << 3) + lrow;
    const int akoff = (tl >> 1) << 2;
    const uint32_t aAddrBase = smem_u32 + (uint32_t)((arow * AS_STRIDE + akoff) * 4);

    const int j_loc = (lane >> 4) & 1;
    const int khalf = (lane >> 3) & 1;
    const uint32_t bTileBase = smem_u32 + (uint32_t)(2 * AS_TILE * 4);
    uint32_t bAddr[2];
#pragma unroll
    for (int jp = 0; jp < 2; jp++) {
        const int n = nBase + 16 * jp + 8 * j_loc + lrow;
        bAddr[jp] = bTileBase + (uint32_t)((n * BS_STRIDE + 4 * khalf) * 4);
    }

    float4 acc[2][4];
#pragma unroll
    for (int t = 0; t < 2; t++)
#pragma unroll
        for (int j = 0; j < 4; j++) acc[t][j] = make_float4(0.f, 0.f, 0.f, 0.f);

    auto cp_A = [&](int kt, int stage) {
        uint32_t* as = As + stage * AS_TILE;
#pragma unroll
        for (int i = 0; i < 4; i++) {
            int row = aRow + 32 * i;
            cp_async16(as + row * AS_STRIDE + aKc,
                       Ar + (size_t)(m0 + row) * 512 + kt * 32 + aKc);
        }
    };

    auto cp_B = [&](int kt, int stage) {
        uint32_t* bs = Bs + stage * BS_TILE;
#pragma unroll
        for (int i = 0; i < 2; i++) {
            int kc = bKc + 16 * i;
            cp_async16(bs + bN * BS_STRIDE + kc,
                       Wr + (size_t)(n0 + bN) * 512 + kt * 32 + kc);
        }
    };

    cp_A(0, 0);
    cp_B(0, 0);
    cp_commit();
    cp_wait<0>();
    __syncthreads();

    const int NKT = 512 / 32;
    for (int kt = 0; kt < NKT; kt++) {
        if (kt + 1 < NKT) {
            cp_A(kt + 1, (kt + 1) & 1);
            cp_B(kt + 1, (kt + 1) & 1);
            cp_commit();
        }

        const uint32_t aStage = aAddrBase + (uint32_t)((kt & 1) * AS_TILE * 4);
        const uint32_t bOff = (uint32_t)((kt & 1) * BS_TILE * 4);

#pragma unroll
        for (int s = 0; s < 4; s++) {
            uint32_t afr[2][4];
            const uint32_t aaddr = aStage + (uint32_t)(s * 32);
            ldmatrix_x4(afr[0][0], afr[0][1], afr[0][2], afr[0][3], aaddr);
            ldmatrix_x4(afr[1][0], afr[1][1], afr[1][2], afr[1][3],
                        aaddr + (uint32_t)(16 * AS_STRIDE * 4));
            uint32_t bfr[2][4];
            ldmatrix_x4(bfr[0][0], bfr[0][1], bfr[0][2], bfr[0][3],
                        bAddr[0] + bOff + (uint32_t)(s * 32));
            ldmatrix_x4(bfr[1][0], bfr[1][1], bfr[1][2], bfr[1][3],
                        bAddr[1] + bOff + (uint32_t)(s * 32));
#pragma unroll
            for (int jp = 0; jp < 2; jp++) {
#pragma unroll
                for (int jl = 0; jl < 2; jl++) {
                    const int j = 2 * jp + jl;
                    const uint32_t b0 = bfr[jp][2 * jl];
                    const uint32_t b1 = bfr[jp][2 * jl + 1];
                    mma_tf32(acc[0][j], afr[0], b0, b1, acc[0][j]);
                    mma_tf32(acc[1][j], afr[1], b0, b1, acc[1][j]);
                }
            }
        }

        if (kt + 1 < NKT) {
            cp_wait<0>();
            __syncthreads();
        }
    }

#pragma unroll
    for (int t = 0; t < 2; t++) {
#pragma unroll
        for (int j = 0; j < 4; j++) {
            const int row = m0 + mBase + 16 * t + g;
            const int col = n0 + nBase + 8 * j + tig * 2;
            float b0 = bias[col], b1 = bias[col + 1];
            float v0 = acc[t][j].x + b0;
            float v1 = acc[t][j].y + b1;
            float v2 = acc[t][j].z + b0;
            float v3 = acc[t][j].w + b1;
            if (EPI == 1) {
                v0 = softplus_f(v0); v1 = softplus_f(v1);
                v2 = softplus_f(v2); v3 = softplus_f(v3);
            }
            *(float2*)(C + (size_t)row * 512 + col) = make_float2(v0, v1);
            *(float2*)(C + (size_t)(row + 8) * 512 + col) = make_float2(v2, v3);
        }
    }
}

// ---------------- bc projection via 3xTF32 tensor cores ----------------
// C[M,32] = (Ahi+Alo)[M,512] @ (Whi+Wlo)[512,32] + bias, dropping lo*lo.
// CTA: M-tile 64, block 128 (4 warps x 16 rows), k-tile 32, double-buffered.
#define BCT_A_TILE (64 * 36)    // per matrix per stage (u32)
#define BCT_B_TILE (32 * 36)
#define BCT_STAGE (2 * BCT_A_TILE + 2 * BCT_B_TILE)   // 6912
#define BCT_SMEM_BYTES (2 * BCT_STAGE * 4)            // 55296

__global__ void __launch_bounds__(128)
bc_tc(const uint32_t* __restrict__ Ahi,
      const uint32_t* __restrict__ Alo,
      const uint32_t* __restrict__ Whi,   // [32][512]
      const uint32_t* __restrict__ Wlo,   // [32][512]
      const float* __restrict__ bB,
      const float* __restrict__ bC,
      float* __restrict__ BC) {
    extern __shared__ uint32_t smem[];

    const int tid  = threadIdx.x;
    const int lane = tid & 31;
    const int warp = tid >> 5;          // 0..3
    const int g    = lane >> 2;
    const int tig  = lane & 3;
    const int mBase = warp * 16;

    const int m0 = blockIdx.x * 64;

    const int aRow = tid >> 3;          // 0..15 (+16*i)
    const int aKc  = (tid & 7) * 4;
    const int bN   = tid >> 2;          // 0..31
    const int bKc  = (tid & 3) * 4;

    const uint32_t smem_u32 = (uint32_t)__cvta_generic_to_shared(smem);

    const int tl   = lane >> 3;
    const int lrow = lane & 7;
    const int arow = mBase + ((tl & 1) << 3) + lrow;
    const int akoff = (tl >> 1) << 2;
    const uint32_t aFragOff = (uint32_t)((arow * 36 + akoff) * 4);

    const int j_loc = (lane >> 4) & 1;
    const int khalf = (lane >> 3) & 1;
    uint32_t bFragOff[2];
#pragma unroll
    for (int jp = 0; jp < 2; jp++) {
        const int n = 16 * jp + 8 * j_loc + lrow;
        bFragOff[jp] = (uint32_t)((n * 36 + 4 * khalf) * 4);
    }

    float4 acc[4];
#pragma unroll
    for (int j = 0; j < 4; j++) acc[j] = make_float4(0.f, 0.f, 0.f, 0.f);

    auto cp_tile = [&](int kt, int stage) {
        uint32_t* base = smem + stage * BCT_STAGE;
#pragma unroll
        for (int i = 0; i < 4; i++) {
            int row = aRow + 16 * i;
            cp_async16(base + row * 36 + aKc,
                       Ahi + (size_t)(m0 + row) * 512 + kt * 32 + aKc);
            cp_async16(base + BCT_A_TILE + row * 36 + aKc,
                       Alo + (size_t)(m0 + row) * 512 + kt * 32 + aKc);
        }
#pragma unroll
        for (int i = 0; i < 2; i++) {
            int kc = bKc + 16 * i;
            cp_async16(base + 2 * BCT_A_TILE + bN * 36 + kc,
                       Whi + (size_t)bN * 512 + kt * 32 + kc);
            cp_async16(base + 2 * BCT_A_TILE + BCT_B_TILE + bN * 36 + kc,
                       Wlo + (size_t)bN * 512 + kt * 32 + kc);
        }
        cp_commit();
    };

    cp_tile(0, 0);
    cp_wait<0>();
    __syncthreads();

    const int NKT = 512 / 32;
    for (int kt = 0; kt < NKT; kt++) {
        if (kt + 1 < NKT) cp_tile(kt + 1, (kt + 1) & 1);

        const uint32_t stageB = smem_u32 + (uint32_t)((kt & 1) * BCT_STAGE * 4);
        const uint32_t aHiB = stageB;
        const uint32_t aLoB = stageB + (uint32_t)(BCT_A_TILE * 4);
        const uint32_t bHiB = stageB + (uint32_t)(2 * BCT_A_TILE * 4);
        const uint32_t bLoB = bHiB + (uint32_t)(BCT_B_TILE * 4);

#pragma unroll
        for (int s = 0; s < 4; s++) {
            const uint32_t so = (uint32_t)(s * 32);
            uint32_t ah[4], al[4];
            ldmatrix_x4(ah[0], ah[1], ah[2], ah[3], aHiB + aFragOff + so);
            ldmatrix_x4(al[0], al[1], al[2], al[3], aLoB + aFragOff + so);
            uint32_t bh[2][4], bl[2][4];
            ldmatrix_x4(bh[0][0], bh[0][1], bh[0][2], bh[0][3],
                        bHiB + bFragOff[0] + so);
            ldmatrix_x4(bh[1][0], bh[1][1], bh[1][2], bh[1][3],
                        bHiB + bFragOff[1] + so);
            ldmatrix_x4(bl[0][0], bl[0][1], bl[0][2], bl[0][3],
                        bLoB + bFragOff[0] + so);
            ldmatrix_x4(bl[1][0], bl[1][1], bl[1][2], bl[1][3],
                        bLoB + bFragOff[1] + so);
#pragma unroll
            for (int jp = 0; jp < 2; jp++) {
#pragma unroll
                for (int jl = 0; jl < 2; jl++) {
                    const int j = 2 * jp + jl;
                    const uint32_t h0 = bh[jp][2 * jl], h1 = bh[jp][2 * jl + 1];
                    const uint32_t l0 = bl[jp][2 * jl], l1 = bl[jp][2 * jl + 1];
                    mma_tf32(acc[j], ah, h0, h1, acc[j]);   // hi*hi
                    mma_tf32(acc[j], ah, l0, l1, acc[j]);   // hi*lo
                    mma_tf32(acc[j], al, h0, h1, acc[j]);   // lo*hi
                }
            }
        }

        if (kt + 1 < NKT) {
            cp_wait<0>();
            __syncthreads();
        }
    }

    // epilogue: bias + store [row][32]
#pragma unroll
    for (int j = 0; j < 4; j++) {
        const int col = 8 * j + tig * 2;
        const float b0 = (col < 16) ? bB[col] : bC[col - 16];
        const float b1 = (col + 1 < 16) ? bB[col + 1] : bC[col + 1 - 16];
        const int r0 = m0 + mBase + g;
        *(float2*)(BC + (size_t)r0 * 32 + col) =
            make_float2(acc[j].x + b0, acc[j].y + b1);
        *(float2*)(BC + (size_t)(r0 + 8) * 32 + col) =
            make_float2(acc[j].z + b0, acc[j].w + b1);
    }
}

// ---------------- scan pass 1: per-chunk carry (A_prod, h_end) ----------------
__global__ void __launch_bounds__(128)
scan_carry(const float* __restrict__ X,
           const float* __restrict__ DT,
           const float* __restrict__ BC,
           const float* __restrict__ A_log,
           float* __restrict__ cA,
           float* __restrict__ cH) {
    __shared__ float sdx[CL][2 * SC_D];
    __shared__ float sB[CL][16];

    const int tid = threadIdx.x;
    const int dl = tid >> 2;
    const int n0 = (tid & 3) * 4;
    const int d0 = blockIdx.x * SC_D;
    const int d  = d0 + dl;
    const int ch = blockIdx.y;
    const int b  = blockIdx.z;

    const float* Xb  = X  + (size_t)b * LL * DD + (size_t)ch * CL * DD;
    const float* DTb = DT + (size_t)b * LL * DD + (size_t)ch * CL * DD;
    const float* BCb = BC + (size_t)b * LL * 32 + (size_t)ch * CL * 32;

#pragma unroll
    for (int i = 0; i < 4; i++) {
        int idx = tid + 128 * i;
        int l = idx >> 3;
        int q = (idx & 7) * 4;
        const float4 dt4 = *(const float4*)(DTb + (size_t)l * DD + d0 + q);
        const float4 x4  = *(const float4*)(Xb  + (size_t)l * DD + d0 + q);
        float4 v0, v1;
        v0.x = dt4.x; v0.y = dt4.x * x4.x; v0.z = dt4.y; v0.w = dt4.y * x4.y;
        v1.x = dt4.z; v1.y = dt4.z * x4.z; v1.z = dt4.w; v1.w = dt4.w * x4.w;
        *(float4*)&sdx[l][2 * q]     = v0;
        *(float4*)&sdx[l][2 * q + 4] = v1;
    }
#pragma unroll
    for (int i = 0; i < 2; i++) {
        int idx = tid + 128 * i;
        int l = idx >> 2;
        int q = (idx & 3) * 4;
        *(float4*)&sB[l][q] = *(const float4*)(BCb + l * 32 + q);
    }
    __syncthreads();

    float Ac2[4];
#pragma unroll
    for (int j = 0; j < 4; j++)
        Ac2[j] = -__expf(A_log[d * NN + n0 + j]) * LOG2E;

    float h[4] = {0.f, 0.f, 0.f, 0.f};
    float Ap[4] = {1.f, 1.f, 1.f, 1.f};

#pragma unroll 4
    for (int l = 0; l < CL; l++) {
        const float2 dd = *(const float2*)&sdx[l][2 * dl];
        const float4 B4 = *(const float4*)&sB[l][n0];
        float a0 = ex2f(dd.x * Ac2[0]);
        float a1 = ex2f(dd.x * Ac2[1]);
        float a2 = ex2f(dd.x * Ac2[2]);
        float a3 = ex2f(dd.x * Ac2[3]);
        h[0] = fmaf(a0, h[0], dd.y * B4.x); Ap[0] *= a0;
        h[1] = fmaf(a1, h[1], dd.y * B4.y); Ap[1] *= a1;
        h[2] = fmaf(a2, h[2], dd.y * B4.z); Ap[2] *= a2;
        h[3] = fmaf(a3, h[3], dd.y * B4.w); Ap[3] *= a3;
    }
    const size_t o = ((size_t)(b * NCH + ch) * DD + d) * NN + n0;
    *(float4*)(cA + o) = make_float4(Ap[0], Ap[1], Ap[2], Ap[3]);
    *(float4*)(cH + o) = make_float4(h[0], h[1], h[2], h[3]);
}

// ---------------- scan pass 2: per-chunk scan + C-contract ----------------
#define SCAN_SMEM_BYTES ((CL * 2 * SC_D + CL * 16 * 2) * 4)   // 24576
__global__ void __launch_bounds__(128)
scan_apply(const float* __restrict__ X,
           const float* __restrict__ DT,
           const float* __restrict__ BC,
           const float* __restrict__ A_log,
           const float* __restrict__ Dskip,
           const float* __restrict__ cA,
           const float* __restrict__ cH,
           uint32_t* __restrict__ Yr) {
    extern __shared__ float ssm[];
    float* sdx = ssm;                          // CL * 64 interleaved (dt|p, x)
    float* sB  = sdx + CL * 2 * SC_D;
    float* sC  = sB + CL * 16;

    const int tid = threadIdx.x;
    const int dl = tid >> 2;
    const int n0 = (tid & 3) * 4;
    const int d0 = blockIdx.x * SC_D;
    const int d  = d0 + dl;
    const int ch = blockIdx.y;
    const int b  = blockIdx.z;

    const float* Xb  = X  + (size_t)b * LL * DD + (size_t)ch * CL * DD;
    const float* DTb = DT + (size_t)b * LL * DD + (size_t)ch * CL * DD;
    const float* BCb = BC + (size_t)b * LL * 32 + (size_t)ch * CL * 32;
    uint32_t*    Yb  = Yr + (size_t)b * LL * DD + (size_t)ch * CL * DD;

#pragma unroll
    for (int i = 0; i < 4; i++) {
        int idx = tid + 128 * i;
        int l = idx >> 3;
        int q = (idx & 7) * 4;
        const float4 dt4 = *(const float4*)(DTb + (size_t)l * DD + d0 + q);
        const float4 x4  = *(const float4*)(Xb  + (size_t)l * DD + d0 + q);
        float4 v0, v1;
        v0.x = dt4.x; v0.y = x4.x; v0.z = dt4.y; v0.w = x4.y;
        v1.x = dt4.z; v1.y = x4.z; v1.z = dt4.w; v1.w = x4.w;
        *(float4*)(sdx + l * 2 * SC_D + 2 * q)     = v0;
        *(float4*)(sdx + l * 2 * SC_D + 2 * q + 4) = v1;
    }
#pragma unroll
    for (int i = 0; i < 2; i++) {
        int idx = tid + 128 * i;
        int l = idx >> 2;
        int q = (idx & 3) * 4;
        *(float4*)(sB + l * 16 + q) = *(const float4*)(BCb + l * 32 + q);
        *(float4*)(sC + l * 16 + q) = *(const float4*)(BCb + l * 32 + 16 + q);
    }

    float h[4] = {0.f, 0.f, 0.f, 0.f};
    {
        const size_t base = ((size_t)b * NCH * DD + d) * NN + n0;
        for (int c = 0; c < ch; c++) {
            const size_t o = base + (size_t)c * (DD * NN);
            const float4 A4 = *(const float4*)(cA + o);
            const float4 H4 = *(const float4*)(cH + o);
            h[0] = fmaf(A4.x, h[0], H4.x);
            h[1] = fmaf(A4.y, h[1], H4.y);
            h[2] = fmaf(A4.z, h[2], H4.z);
            h[3] = fmaf(A4.w, h[3], H4.w);
        }
    }

    float Ac2[4];
#pragma unroll
    for (int j = 0; j < 4; j++)
        Ac2[j] = -__expf(A_log[d * NN + n0 + j]) * LOG2E;

    __syncthreads();

#pragma unroll 4
    for (int l = 0; l < CL; l++) {
        const float2 dd = *(const float2*)(sdx + l * 2 * SC_D + 2 * dl);
        const float dtx = dd.x * dd.y;
        const float4 B4 = *(const float4*)(sB + l * 16 + n0);
        const float4 C4 = *(const float4*)(sC + l * 16 + n0);
        float a0 = ex2f(dd.x * Ac2[0]);
        float a1 = ex2f(dd.x * Ac2[1]);
        float a2 = ex2f(dd.x * Ac2[2]);
        float a3 = ex2f(dd.x * Ac2[3]);
        h[0] = fmaf(a0, h[0], dtx * B4.x);
        h[1] = fmaf(a1, h[1], dtx * B4.y);
        h[2] = fmaf(a2, h[2], dtx * B4.z);
        h[3] = fmaf(a3, h[3], dtx * B4.w);
        float p01 = fmaf(C4.y, h[1], C4.x * h[0]);
        float p23 = fmaf(C4.w, h[3], C4.z * h[2]);
        float p = p01 + p23;
        p += __shfl_xor_sync(0xffffffffu, p, 1, 4);
        p += __shfl_xor_sync(0xffffffffu, p, 2, 4);
        if (n0 == 0) sdx[l * 2 * SC_D + 2 * dl] = p;
    }
    __syncthreads();

#pragma unroll
    for (int i = 0; i < 4; i++) {
        int idx = tid + 128 * i;
        int l = idx >> 3;
        int q = (idx & 7) * 4;
        const float4 dk = *(const float4*)(Dskip + d0 + q);
        const float4 f0 = *(const float4*)(sdx + l * 2 * SC_D + 2 * q);
        const float4 f1 = *(const float4*)(sdx + l * 2 * SC_D + 2 * q + 4);
        uint4 o;
        o.x = f2tf32(gelu_f(fmaf(dk.x, f0.y, f0.x)));
        o.y = f2tf32(gelu_f(fmaf(dk.y, f0.w, f0.z)));
        o.z = f2tf32(gelu_f(fmaf(dk.z, f1.y, f1.x)));
        o.w = f2tf32(gelu_f(fmaf(dk.w, f1.w, f1.z)));
        *(uint4*)(Yb + (size_t)l * DD + d0 + q) = o;
    }
}

// ---------------- layernorm + residual: one warp per row ----------------
// Writes fp32 Hout AND tf32 hi/lo copies (GEMM + bc inputs).
__global__ void __launch_bounds__(256)
ln_res_kernel(const float* __restrict__ Hin,
              const float* __restrict__ Y2,
              const float* __restrict__ g,
              const float* __restrict__ bb,
              float* __restrict__ Hout,
              uint32_t* __restrict__ Hr,
              uint32_t* __restrict__ Hl) {
    const int lane = threadIdx.x & 31;
    const int wrp  = threadIdx.x >> 5;
    const int row  = blockIdx.x * 8 + wrp;
    const float* yr = Y2 + (size_t)row * DD;

    float4 v[4];
    float s = 0.f;
#pragma unroll
    for (int j = 0; j < 4; j++) {
        v[j] = *(const float4*)(yr + lane * 4 + j * 128);
        s += (v[j].x + v[j].y) + (v[j].z + v[j].w);
    }
#pragma unroll
    for (int o = 16; o > 0; o >>= 1) s += __shfl_xor_sync(0xffffffffu, s, o);
    const float mean = s * (1.f / DD);

    float sq = 0.f;
#pragma unroll
    for (int j = 0; j < 4; j++) {
        float d0 = v[j].x - mean, d1 = v[j].y - mean;
        float d2 = v[j].z - mean, d3 = v[j].w - mean;
        sq += (d0 * d0 + d1 * d1) + (d2 * d2 + d3 * d3);
    }
#pragma unroll
    for (int o = 16; o > 0; o >>= 1) sq += __shfl_xor_sync(0xffffffffu, sq, o);
    const float rstd = rsqrtf(sq * (1.f / DD) + 1e-5f);

#pragma unroll
    for (int j = 0; j < 4; j++) {
        const int col = lane * 4 + j * 128;
        const float4 gg = *(const float4*)(g + col);
        const float4 bv = *(const float4*)(bb + col);
        const float4 hi = *(const float4*)(Hin + (size_t)row * DD + col);
        float4 o;
        o.x = hi.x + (v[j].x - mean) * rstd * gg.x + bv.x;
        o.y = hi.y + (v[j].y - mean) * rstd * gg.y + bv.y;
        o.z = hi.z + (v[j].z - mean) * rstd * gg.z + bv.z;
        o.w = hi.w + (v[j].w - mean) * rstd * gg.w + bv.w;
        *(float4*)(Hout + (size_t)row * DD + col) = o;
        uint4 rh, rl;
        rh.x = f2tf32(o.x); rh.y = f2tf32(o.y);
        rh.z = f2tf32(o.z); rh.w = f2tf32(o.w);
        rl.x = f2tf32(o.x - __uint_as_float(rh.x));
        rl.y = f2tf32(o.y - __uint_as_float(rh.y));
        rl.z = f2tf32(o.z - __uint_as_float(rh.z));
        rl.w = f2tf32(o.w - __uint_as_float(rh.w));
        *(uint4*)(Hr + (size_t)row * DD + col) = rh;
        *(uint4*)(Hl + (size_t)row * DD + col) = rl;
    }
}

// ---------------- launch ----------------
extern "C" void kernel_launch(void* const* d_in, const int* in_sizes, int n_in,
                              void* d_out, int out_size) {
    const float* x      = (const float*)d_in[0];
    const float* A_log  = (const float*)d_in[1];
    const float* W_B    = (const float*)d_in[2];
    const float* b_B    = (const float*)d_in[3];
    const float* W_C    = (const float*)d_in[4];
    const float* b_C    = (const float*)d_in[5];
    const float* W_dt   = (const float*)d_in[6];
    const float* b_dt   = (const float*)d_in[7];
    const float* D_skip = (const float*)d_in[8];
    const float* W_mix  = (const float*)d_in[9];
    const float* b_mix  = (const float*)d_in[10];
    const float* ln_g   = (const float*)d_in[11];
    const float* ln_b   = (const float*)d_in[12];
    const float* W_dec  = (const float*)d_in[13];
    const float* b_dec  = (const float*)d_in[14];
    float* out = (float*)d_out;

    float *p_dt, *p_bc, *p_y2, *p_hA, *p_hB, *p_cA, *p_cH;
    uint32_t *p_wr, *p_xr, *p_xl, *p_yr, *p_hr, *p_hl, *p_bcw;
    cudaGetSymbolAddress((void**)&p_dt, g_dt);
    cudaGetSymbolAddress((void**)&p_bc, g_bc);
    cudaGetSymbolAddress((void**)&p_y2, g_y2);
    cudaGetSymbolAddress((void**)&p_hA, g_hA);
    cudaGetSymbolAddress((void**)&p_hB, g_hB);
    cudaGetSymbolAddress((void**)&p_cA, g_cA);
    cudaGetSymbolAddress((void**)&p_cH, g_cH);
    cudaGetSymbolAddress((void**)&p_wr, g_wr);
    cudaGetSymbolAddress((void**)&p_xr, g_xr);
    cudaGetSymbolAddress((void**)&p_xl, g_xl);
    cudaGetSymbolAddress((void**)&p_yr, g_yr);
    cudaGetSymbolAddress((void**)&p_hr, g_hr);
    cudaGetSymbolAddress((void**)&p_hl, g_hl);
    cudaGetSymbolAddress((void**)&p_bcw, g_bcw);

    cudaFuncSetAttribute(gemm_tc<0>, cudaFuncAttributeMaxDynamicSharedMemorySize,
                         GEMM_SMEM_BYTES);
    cudaFuncSetAttribute(gemm_tc<1>, cudaFuncAttributeMaxDynamicSharedMemorySize,
                         GEMM_SMEM_BYTES);
    cudaFuncSetAttribute(bc_tc, cudaFuncAttributeMaxDynamicSharedMemorySize,
                         BCT_SMEM_BYTES);
    cudaFuncSetAttribute(scan_apply, cudaFuncAttributeMaxDynamicSharedMemorySize,
                         SCAN_SMEM_BYTES);

    // one-time prep: weights (tf32 / transposed / hi-lo) + x hi/lo
    {
        dim3 pgrid(DD / 32, DD / 32, 5);
        dim3 pblk(32, 8);
        prep_w<<<pgrid, pblk>>>(W_dt, W_mix, W_dec);
        prep_x<<<MM * DD / 4 / 256, 256>>>(x);
        prep_bcw<<<NLAYERS * 32 * DD / 256, 256>>>(W_B, W_C);
    }

    const dim3 gemmGrid(DD / 64, MM / 128);       // (8, 64) = 512 CTAs
    const dim3 scanGrid(DD / SC_D, NCH, BB);      // (16, 32, 4)

    const float* hin = x;
    const uint32_t* hinr = p_xr;
    const uint32_t* hinl = p_xl;
    float* houts[2] = { p_hA, p_hB };

    for (int l = 0; l < NLAYERS; l++) {
        gemm_tc<1><<<gemmGrid, 256, GEMM_SMEM_BYTES>>>(
            hinr, p_wr + (size_t)l * WSEG, b_dt + l * DD, p_dt);
        bc_tc<<<MM / 64, 128, BCT_SMEM_BYTES>>>(
            hinr, hinl,
            p_bcw + (size_t)(l * 2 + 0) * 32 * DD,
            p_bcw + (size_t)(l * 2 + 1) * 32 * DD,
            b_B + l * NN, b_C + l * NN, p_bc);
        scan_carry<<<scanGrid, 128>>>(hin, p_dt, p_bc,
                                      A_log + (size_t)l * DD * NN, p_cA, p_cH);
        scan_apply<<<scanGrid, 128, SCAN_SMEM_BYTES>>>(
            hin, p_dt, p_bc, A_log + (size_t)l * DD * NN,
            D_skip + l * DD, p_cA, p_cH, p_yr);
        gemm_tc<0><<<gemmGrid, 256, GEMM_SMEM_BYTES>>>(
            p_yr, p_wr + (size_t)(2 + l) * WSEG, b_mix + l * DD, p_y2);
        ln_res_kernel<<<MM / 8, 256>>>(hin, p_y2, ln_g + l * DD, ln_b + l * DD,
                                       houts[l], p_hr, p_hl);
        hin = houts[l];
        hinr = p_hr;
        hinl = p_hl;
    }

    gemm_tc<0><<<gemmGrid, 256, GEMM_SMEM_BYTES>>>(p_hr, p_wr + (size_t)4 * WSEG,
                                                   b_dec, out);
}